// round 11
// baseline (speedup 1.0000x reference)
#include <cuda_runtime.h>
#include <cuda_fp16.h>
#include <stdint.h>

#define N_NODES 100000
#define N_EDGES 3200000
#define D 128
#define LN_EPS 1e-5f

// ---------------------------------------------------------------------------
// Device-global scratch (no allocations allowed).
// ---------------------------------------------------------------------------
__device__ __half g_Hh[(size_t)N_NODES * D];   // LN(X) @ W^T + b, fp16
__device__ int   g_off[N_NODES + 1];           // CSR offsets (by dst)
__device__ int   g_cur[N_NODES];               // bucket cursors
__device__ int2  g_sw[N_EDGES];                // packed (src, w_bits) sorted by dst
__device__ int   g_bsum[128];                  // scan block sums

// ===========================================================================
// Kernel A: standalone edge histogram (int4-vectorized).
// ===========================================================================
#define HIST_BLOCKS 512
__global__ void __launch_bounds__(256)
hist_kernel(const int* __restrict__ edst, int E) {
    const int n4     = E >> 2;
    const int4* p    = reinterpret_cast<const int4*>(edst);
    const int stride = HIST_BLOCKS * 256;
    for (int i = blockIdx.x * 256 + threadIdx.x; i < n4; i += stride) {
        const int4 v = __ldcs(&p[i]);
        atomicAdd(&g_off[v.x + 1], 1);
        atomicAdd(&g_off[v.y + 1], 1);
        atomicAdd(&g_off[v.z + 1], 1);
        atomicAdd(&g_off[v.w + 1], 1);
    }
    // E is a multiple of 4 here (3.2M); no tail.
}

// ===========================================================================
// Scan: chunk-scan + fused (bsum-prefix + add + cursor init)
// ===========================================================================
__device__ __forceinline__ int warp_incl_scan(int v, int lane) {
    #pragma unroll
    for (int off = 1; off < 32; off <<= 1) {
        int t = __shfl_up_sync(0xffffffffu, v, off);
        if (lane >= off) v += t;
    }
    return v;
}

__global__ void scan_chunk_kernel(int n) {        // blockDim = 1024
    __shared__ int wsum[32];
    const int tid  = threadIdx.x;
    const int lane = tid & 31;
    const int wid  = tid >> 5;
    const int gi   = blockIdx.x * 1024 + tid;
    int v = (gi < n) ? g_off[gi] : 0;
    v = warp_incl_scan(v, lane);
    if (lane == 31) wsum[wid] = v;
    __syncthreads();
    if (wid == 0) wsum[lane] = warp_incl_scan(wsum[lane], lane);
    __syncthreads();
    if (wid > 0) v += wsum[wid - 1];
    if (gi < n) g_off[gi] = v;
    if (tid == 1023) g_bsum[blockIdx.x] = v;
}

__global__ void scan_add_fused_kernel(int n, int nb) {   // blockDim = 1024
    __shared__ int bs[128];
    const int tid = threadIdx.x;
    if (tid < nb) bs[tid] = g_bsum[tid];
    __syncthreads();
    if (tid == 0) {                                // serial prefix of <=128 vals
        int run = 0;
        for (int i = 0; i < nb; ++i) { run += bs[i]; bs[i] = run; }
    }
    __syncthreads();
    const int gi = blockIdx.x * 1024 + tid;
    if (gi >= n) return;
    const int add = (blockIdx.x > 0) ? bs[blockIdx.x - 1] : 0;
    const int val = g_off[gi] + add;
    g_off[gi] = val;
    if (gi < N_NODES) g_cur[gi] = val;
}

// ===========================================================================
// Kernel B: fused [LN + Linear -> g_Hh]  ||  [edge reorder], interleaved roles.
//   Every 8th block (bid%8==7) is a reorder block; others are GEMM blocks.
//   Reorder (mem/atomic-bound) hides under the GEMM (FMA-bound) waves.
// ===========================================================================
#define ROWS_PB 32
#define LN_BLOCKS (N_NODES / ROWS_PB)              // 3125
#define RORD_BLOCKS 446
#define TOTAL_BLOCKS 3572                          // 3126 gemm-role + 446 reorder
#define WS_PITCH 132
#define XN2_OFF (128 * WS_PITCH)                   // in floats
#define SMEM_BYTES ((128 * WS_PITCH) * 4 + ROWS_PB * D * 8)

__global__ void __launch_bounds__(256, 2)
ln_gemm_reorder_kernel(const float* __restrict__ X,
                       const float* __restrict__ gamma,
                       const float* __restrict__ beta,
                       const float* __restrict__ W,
                       const float* __restrict__ bias,
                       const int* __restrict__ esrc,
                       const int* __restrict__ edst,
                       const float* __restrict__ ew, int E) {
    const int tid = threadIdx.x;
    const int bid = blockIdx.x;

    // ---- reorder role (every 8th block) ---------------------------------
    if ((bid & 7) == 7) {
        const int rid    = bid >> 3;               // 0..RORD_BLOCKS-1
        const int stride = RORD_BLOCKS * 256;
        for (int e = rid * 256 + tid; e < E; e += stride) {
            const int dst = __ldcs(&edst[e]);
            const int pos = atomicAdd(&g_cur[dst], 1);
            g_sw[pos] = make_int2(__ldcs(&esrc[e]),
                                  __float_as_int(__ldcs(&ew[e])));
        }
        return;
    }

    // ---- LN + GEMM role -------------------------------------------------
    const int gb = bid - (bid >> 3);               // gemm block index
    if (gb >= LN_BLOCKS) return;

    extern __shared__ float smem[];
    float*  Ws  = smem;                                       // [128][132]
    float2* xn2 = reinterpret_cast<float2*>(smem + XN2_OFF);  // splatted {x,x}

    const int lane = tid & 31;
    const int warp = tid >> 5;
    const int row0 = gb * ROWS_PB;

    // Load + transpose W into smem.
    for (int i = tid; i < 128 * 128; i += 256) {
        int o = i >> 7;
        int d = i & 127;
        Ws[d * WS_PITCH + o] = W[i];
    }

    // LayerNorm: 8 warps x 4 rows each; write splatted pairs {h,h}.
    #pragma unroll
    for (int rr = 0; rr < ROWS_PB / 8; ++rr) {
        const int r   = warp + rr * 8;
        const int row = row0 + r;
        const float4 v = reinterpret_cast<const float4*>(X + (size_t)row * D)[lane];
        float s  = v.x + v.y + v.z + v.w;
        float sq = v.x * v.x + v.y * v.y + v.z * v.z + v.w * v.w;
        #pragma unroll
        for (int off = 16; off; off >>= 1) {
            s  += __shfl_xor_sync(0xffffffffu, s,  off);
            sq += __shfl_xor_sync(0xffffffffu, sq, off);
        }
        const float mu  = s * (1.0f / D);
        const float var = sq * (1.0f / D) - mu * mu;
        const float inv = rsqrtf(var + LN_EPS);
        const float4 g  = reinterpret_cast<const float4*>(gamma)[lane];
        const float4 be = reinterpret_cast<const float4*>(beta)[lane];
        float h0 = (v.x - mu) * inv * g.x + be.x;
        float h1 = (v.y - mu) * inv * g.y + be.y;
        float h2 = (v.z - mu) * inv * g.z + be.z;
        float h3 = (v.w - mu) * inv * g.w + be.w;
        float2* xp = xn2 + r * D + lane * 4;
        xp[0] = make_float2(h0, h0);
        xp[1] = make_float2(h1, h1);
        xp[2] = make_float2(h2, h2);
        xp[3] = make_float2(h3, h3);
    }
    __syncthreads();

    // GEMM: thread (tr, tc): rows tr*4..+3, cols tc*4..+3. f32x2 packed FMA.
    const int tc = tid & 31;
    const int tr = tid >> 5;

    unsigned long long acc01[4], acc23[4];
    #pragma unroll
    for (int i = 0; i < 4; ++i) { acc01[i] = 0ull; acc23[i] = 0ull; }

    const unsigned long long* xbase =
        reinterpret_cast<const unsigned long long*>(xn2) + tr * 4 * D;
    const float* wbase = Ws + (tc << 2);

    #pragma unroll 4
    for (int d = 0; d < D; ++d) {
        const ulonglong2 wv =
            *reinterpret_cast<const ulonglong2*>(wbase + d * WS_PITCH);
        #pragma unroll
        for (int r = 0; r < 4; ++r) {
            const unsigned long long xs = xbase[r * D + d];   // {x,x}
            asm("fma.rn.f32x2 %0, %1, %2, %0;" : "+l"(acc01[r]) : "l"(xs), "l"(wv.x));
            asm("fma.rn.f32x2 %0, %1, %2, %0;" : "+l"(acc23[r]) : "l"(xs), "l"(wv.y));
        }
    }

    const float4 bv = reinterpret_cast<const float4*>(bias)[tc];
    #pragma unroll
    for (int r = 0; r < 4; ++r) {
        const int row = row0 + tr * 4 + r;
        const float hx = __uint_as_float((unsigned)(acc01[r] & 0xffffffffull)) + bv.x;
        const float hy = __uint_as_float((unsigned)(acc01[r] >> 32))           + bv.y;
        const float hz = __uint_as_float((unsigned)(acc23[r] & 0xffffffffull)) + bv.z;
        const float hw = __uint_as_float((unsigned)(acc23[r] >> 32))           + bv.w;
        const __half2 p01 = __floats2half2_rn(hx, hy);
        const __half2 p23 = __floats2half2_rn(hz, hw);
        uint2 st;
        st.x = *reinterpret_cast<const unsigned*>(&p01);
        st.y = *reinterpret_cast<const unsigned*>(&p23);
        reinterpret_cast<uint2*>(g_Hh + (size_t)row * D)[tc] = st;
    }
}

// ===========================================================================
// Aggregate: one warp per dst node, unroll-4 with front-batched gathers.
//   Lane loads uint2 = 8B of the 256B fp16 row; fp32 accumulate.
// ===========================================================================
__device__ __forceinline__ void fma_h4(float4& acc, uint2 raw, float w) {
    const __half2 a = *reinterpret_cast<const __half2*>(&raw.x);
    const __half2 b = *reinterpret_cast<const __half2*>(&raw.y);
    const float2 f01 = __half22float2(a);
    const float2 f23 = __half22float2(b);
    acc.x = fmaf(w, f01.x, acc.x);
    acc.y = fmaf(w, f01.y, acc.y);
    acc.z = fmaf(w, f23.x, acc.z);
    acc.w = fmaf(w, f23.y, acc.w);
}

__global__ void __launch_bounds__(256)
aggregate_kernel(const float* __restrict__ X, float* __restrict__ out) {
    const int gw = (blockIdx.x * blockDim.x + threadIdx.x) >> 5;
    if (gw >= N_NODES) return;
    const int lane = threadIdx.x & 31;

    const int beg = g_off[gw];
    const int end = g_off[gw + 1];

    float4 acc = make_float4(0.f, 0.f, 0.f, 0.f);
    int e = beg;

    for (; e + 3 < end; e += 4) {
        const int2 sw0 = __ldcs(&g_sw[e]);
        const int2 sw1 = __ldcs(&g_sw[e + 1]);
        const int2 sw2 = __ldcs(&g_sw[e + 2]);
        const int2 sw3 = __ldcs(&g_sw[e + 3]);
        const uint2 r0 = __ldg(
            reinterpret_cast<const uint2*>(g_Hh + (size_t)sw0.x * D) + lane);
        const uint2 r1 = __ldg(
            reinterpret_cast<const uint2*>(g_Hh + (size_t)sw1.x * D) + lane);
        const uint2 r2 = __ldg(
            reinterpret_cast<const uint2*>(g_Hh + (size_t)sw2.x * D) + lane);
        const uint2 r3 = __ldg(
            reinterpret_cast<const uint2*>(g_Hh + (size_t)sw3.x * D) + lane);
        fma_h4(acc, r0, __int_as_float(sw0.y));
        fma_h4(acc, r1, __int_as_float(sw1.y));
        fma_h4(acc, r2, __int_as_float(sw2.y));
        fma_h4(acc, r3, __int_as_float(sw3.y));
    }
    for (; e < end; ++e) {
        const int2 sw = __ldcs(&g_sw[e]);
        const uint2 r = __ldg(
            reinterpret_cast<const uint2*>(g_Hh + (size_t)sw.x * D) + lane);
        fma_h4(acc, r, __int_as_float(sw.y));
    }

    const float4 xv =
        __ldcs(reinterpret_cast<const float4*>(X + (size_t)gw * D) + lane);
    float4 o;
    o.x = fmaxf(acc.x, 0.f) + xv.x;
    o.y = fmaxf(acc.y, 0.f) + xv.y;
    o.z = fmaxf(acc.z, 0.f) + xv.z;
    o.w = fmaxf(acc.w, 0.f) + xv.w;
    __stcs(reinterpret_cast<float4*>(out + (size_t)gw * D) + lane, o);
}

// ===========================================================================
extern "C" void kernel_launch(void* const* d_in, const int* in_sizes, int n_in,
                              void* d_out, int out_size) {
    const float* X     = (const float*)d_in[0];
    const int*   esrc  = (const int*)d_in[1];
    const int*   edst  = (const int*)d_in[2];
    const float* ew    = (const float*)d_in[3];
    const float* gamma = (const float*)d_in[4];
    const float* beta  = (const float*)d_in[5];
    const float* W     = (const float*)d_in[6];
    const float* bias  = (const float*)d_in[7];
    float* out         = (float*)d_out;
    const int E        = in_sizes[1];

    cudaFuncSetAttribute(ln_gemm_reorder_kernel,
                         cudaFuncAttributeMaxDynamicSharedMemorySize,
                         SMEM_BYTES);

    void* off_ptr = nullptr;
    cudaGetSymbolAddress(&off_ptr, g_off);
    cudaMemsetAsync(off_ptr, 0, (N_NODES + 1) * sizeof(int));

    const int n  = N_NODES + 1;
    const int nb = (n + 1023) / 1024;                 // 98

    hist_kernel<<<HIST_BLOCKS, 256>>>(edst, E);
    scan_chunk_kernel<<<nb, 1024>>>(n);
    scan_add_fused_kernel<<<nb, 1024>>>(n, nb);

    ln_gemm_reorder_kernel<<<TOTAL_BLOCKS, 256, SMEM_BYTES>>>(
        X, gamma, beta, W, bias, esrc, edst, ew, E);

    aggregate_kernel<<<(N_NODES * 32 + 255) / 256, 256>>>(X, out);
}

// round 12
// speedup vs baseline: 1.1056x; 1.1056x over previous
#include <cuda_runtime.h>
#include <cuda_fp16.h>
#include <stdint.h>

#define N_NODES 100000
#define N_EDGES 3200000
#define D 128
#define LN_EPS 1e-5f

// ---------------------------------------------------------------------------
// Device-global scratch (no allocations allowed).
// ---------------------------------------------------------------------------
__device__ __half g_Hh[(size_t)N_NODES * D];   // LN(X) @ W^T + b, fp16
__device__ int   g_off[N_NODES + 1];           // CSR offsets (by dst)
__device__ int   g_cur[N_NODES];               // bucket cursors
__device__ int2  g_sw[N_EDGES];                // packed (src, w_bits) sorted by dst
__device__ int   g_bsum[128];                  // scan block sums

// ===========================================================================
// Kernel A: standalone edge histogram (int4-vectorized).
// ===========================================================================
#define HIST_BLOCKS 512
__global__ void __launch_bounds__(256)
hist_kernel(const int* __restrict__ edst, int E) {
    const int n4     = E >> 2;
    const int4* p    = reinterpret_cast<const int4*>(edst);
    const int stride = HIST_BLOCKS * 256;
    const int gid    = blockIdx.x * 256 + threadIdx.x;
    for (int i = gid; i < n4; i += stride) {
        const int4 v = __ldcs(&p[i]);
        atomicAdd(&g_off[v.x + 1], 1);
        atomicAdd(&g_off[v.y + 1], 1);
        atomicAdd(&g_off[v.z + 1], 1);
        atomicAdd(&g_off[v.w + 1], 1);
    }
    for (int e = (n4 << 2) + gid; e < E; e += stride)      // tail (none for 3.2M)
        atomicAdd(&g_off[edst[e] + 1], 1);
}

// ===========================================================================
// Scan: chunk-scan + fused (bsum-prefix + add + cursor init)
// ===========================================================================
__device__ __forceinline__ int warp_incl_scan(int v, int lane) {
    #pragma unroll
    for (int off = 1; off < 32; off <<= 1) {
        int t = __shfl_up_sync(0xffffffffu, v, off);
        if (lane >= off) v += t;
    }
    return v;
}

__global__ void scan_chunk_kernel(int n) {        // blockDim = 1024
    __shared__ int wsum[32];
    const int tid  = threadIdx.x;
    const int lane = tid & 31;
    const int wid  = tid >> 5;
    const int gi   = blockIdx.x * 1024 + tid;
    int v = (gi < n) ? g_off[gi] : 0;
    v = warp_incl_scan(v, lane);
    if (lane == 31) wsum[wid] = v;
    __syncthreads();
    if (wid == 0) wsum[lane] = warp_incl_scan(wsum[lane], lane);
    __syncthreads();
    if (wid > 0) v += wsum[wid - 1];
    if (gi < n) g_off[gi] = v;
    if (tid == 1023) g_bsum[blockIdx.x] = v;
}

__global__ void scan_add_fused_kernel(int n, int nb) {   // blockDim = 1024
    __shared__ int bs[128];
    const int tid = threadIdx.x;
    if (tid < nb) bs[tid] = g_bsum[tid];
    __syncthreads();
    if (tid == 0) {
        int run = 0;
        for (int i = 0; i < nb; ++i) { run += bs[i]; bs[i] = run; }
    }
    __syncthreads();
    const int gi = blockIdx.x * 1024 + tid;
    if (gi >= n) return;
    const int add = (blockIdx.x > 0) ? bs[blockIdx.x - 1] : 0;
    const int val = g_off[gi] + add;
    g_off[gi] = val;
    if (gi < N_NODES) g_cur[gi] = val;
}

// ===========================================================================
// Kernel C: edge reorder into dst-CSR buckets.
// ===========================================================================
__global__ void __launch_bounds__(256)
reorder_kernel(const int* __restrict__ esrc,
               const int* __restrict__ edst,
               const float* __restrict__ ew, int E) {
    const int stride = gridDim.x * blockDim.x;
    for (int e = blockIdx.x * blockDim.x + threadIdx.x; e < E; e += stride) {
        const int dst = __ldcs(&edst[e]);
        const int pos = atomicAdd(&g_cur[dst], 1);
        g_sw[pos] = make_int2(__ldcs(&esrc[e]), __float_as_int(__ldcs(&ew[e])));
    }
}

// ===========================================================================
// Kernel D: fused LayerNorm + Linear (X -> g_Hh, fp16), f32x2 packed FMA.
//   ROWS_PB=64 rows/block, 256 threads, 1 block/SM (131KB smem).
//   Thread (tr=warp, tc=lane): 8 rows x 4 cols -> per d: 9 LDS + 16 FFMA2
//   => FMA-pipe-bound.
// ===========================================================================
#define ROWS_PB 64
#define WS_PITCH 132
#define XN2_OFF (128 * WS_PITCH)                   // in floats
#define SMEM_BYTES ((128 * WS_PITCH) * 4 + ROWS_PB * D * 8)

__global__ void __launch_bounds__(256, 1)
ln_linear_kernel(const float* __restrict__ X,
                 const float* __restrict__ gamma,
                 const float* __restrict__ beta,
                 const float* __restrict__ W,
                 const float* __restrict__ bias) {
    extern __shared__ float smem[];
    float*  Ws  = smem;                                       // [128][132]
    float2* xn2 = reinterpret_cast<float2*>(smem + XN2_OFF);  // splatted {x,x}

    const int tid  = threadIdx.x;
    const int lane = tid & 31;
    const int warp = tid >> 5;
    const int row0 = blockIdx.x * ROWS_PB;

    // Load + transpose W into smem.
    for (int i = tid; i < 128 * 128; i += 256) {
        int o = i >> 7;
        int d = i & 127;
        Ws[d * WS_PITCH + o] = W[i];
    }

    // LayerNorm: 8 warps x 8 rows each; write splatted pairs {h,h}.
    #pragma unroll
    for (int rr = 0; rr < ROWS_PB / 8; ++rr) {
        const int r   = warp + rr * 8;
        const int row = row0 + r;
        float4 v = make_float4(0.f, 0.f, 0.f, 0.f);
        if (row < N_NODES)
            v = reinterpret_cast<const float4*>(X + (size_t)row * D)[lane];
        float s  = v.x + v.y + v.z + v.w;
        float sq = v.x * v.x + v.y * v.y + v.z * v.z + v.w * v.w;
        #pragma unroll
        for (int off = 16; off; off >>= 1) {
            s  += __shfl_xor_sync(0xffffffffu, s,  off);
            sq += __shfl_xor_sync(0xffffffffu, sq, off);
        }
        const float mu  = s * (1.0f / D);
        const float var = sq * (1.0f / D) - mu * mu;
        const float inv = rsqrtf(var + LN_EPS);
        const float4 g  = reinterpret_cast<const float4*>(gamma)[lane];
        const float4 be = reinterpret_cast<const float4*>(beta)[lane];
        float h0 = (v.x - mu) * inv * g.x + be.x;
        float h1 = (v.y - mu) * inv * g.y + be.y;
        float h2 = (v.z - mu) * inv * g.z + be.z;
        float h3 = (v.w - mu) * inv * g.w + be.w;
        float2* xp = xn2 + r * D + lane * 4;
        xp[0] = make_float2(h0, h0);
        xp[1] = make_float2(h1, h1);
        xp[2] = make_float2(h2, h2);
        xp[3] = make_float2(h3, h3);
    }
    __syncthreads();

    // GEMM: thread (tr, tc): rows tr*8..+7, cols tc*4..+3. f32x2 packed FMA.
    const int tc = tid & 31;
    const int tr = tid >> 5;

    unsigned long long acc01[8], acc23[8];
    #pragma unroll
    for (int i = 0; i < 8; ++i) { acc01[i] = 0ull; acc23[i] = 0ull; }

    const unsigned long long* xbase =
        reinterpret_cast<const unsigned long long*>(xn2) + tr * 8 * D;
    const float* wbase = Ws + (tc << 2);

    #pragma unroll 2
    for (int d = 0; d < D; ++d) {
        const ulonglong2 wv =
            *reinterpret_cast<const ulonglong2*>(wbase + d * WS_PITCH);
        #pragma unroll
        for (int r = 0; r < 8; ++r) {
            const unsigned long long xs = xbase[r * D + d];   // {x,x} broadcast
            asm("fma.rn.f32x2 %0, %1, %2, %0;" : "+l"(acc01[r]) : "l"(xs), "l"(wv.x));
            asm("fma.rn.f32x2 %0, %1, %2, %0;" : "+l"(acc23[r]) : "l"(xs), "l"(wv.y));
        }
    }

    const float4 bv = reinterpret_cast<const float4*>(bias)[tc];
    #pragma unroll
    for (int r = 0; r < 8; ++r) {
        const int row = row0 + tr * 8 + r;
        if (row < N_NODES) {
            const float hx = __uint_as_float((unsigned)(acc01[r] & 0xffffffffull)) + bv.x;
            const float hy = __uint_as_float((unsigned)(acc01[r] >> 32))           + bv.y;
            const float hz = __uint_as_float((unsigned)(acc23[r] & 0xffffffffull)) + bv.z;
            const float hw = __uint_as_float((unsigned)(acc23[r] >> 32))           + bv.w;
            const __half2 p01 = __floats2half2_rn(hx, hy);
            const __half2 p23 = __floats2half2_rn(hz, hw);
            uint2 st;
            st.x = *reinterpret_cast<const unsigned*>(&p01);
            st.y = *reinterpret_cast<const unsigned*>(&p23);
            reinterpret_cast<uint2*>(g_Hh + (size_t)row * D)[tc] = st;
        }
    }
}

// ===========================================================================
// Kernel E: aggregate. One warp per dst node, unroll-4 front-batched gathers.
//   out = relu(sum w*H[src]) + X.
// ===========================================================================
__device__ __forceinline__ void fma_h4(float4& acc, uint2 raw, float w) {
    const __half2 a = *reinterpret_cast<const __half2*>(&raw.x);
    const __half2 b = *reinterpret_cast<const __half2*>(&raw.y);
    const float2 f01 = __half22float2(a);
    const float2 f23 = __half22float2(b);
    acc.x = fmaf(w, f01.x, acc.x);
    acc.y = fmaf(w, f01.y, acc.y);
    acc.z = fmaf(w, f23.x, acc.z);
    acc.w = fmaf(w, f23.y, acc.w);
}

__global__ void __launch_bounds__(256)
aggregate_kernel(const float* __restrict__ X, float* __restrict__ out) {
    const int gw = (blockIdx.x * blockDim.x + threadIdx.x) >> 5;
    if (gw >= N_NODES) return;
    const int lane = threadIdx.x & 31;

    const int beg = g_off[gw];
    const int end = g_off[gw + 1];

    float4 acc = make_float4(0.f, 0.f, 0.f, 0.f);
    int e = beg;

    for (; e + 3 < end; e += 4) {
        const int2 sw0 = __ldcs(&g_sw[e]);
        const int2 sw1 = __ldcs(&g_sw[e + 1]);
        const int2 sw2 = __ldcs(&g_sw[e + 2]);
        const int2 sw3 = __ldcs(&g_sw[e + 3]);
        const uint2 r0 = __ldg(
            reinterpret_cast<const uint2*>(g_Hh + (size_t)sw0.x * D) + lane);
        const uint2 r1 = __ldg(
            reinterpret_cast<const uint2*>(g_Hh + (size_t)sw1.x * D) + lane);
        const uint2 r2 = __ldg(
            reinterpret_cast<const uint2*>(g_Hh + (size_t)sw2.x * D) + lane);
        const uint2 r3 = __ldg(
            reinterpret_cast<const uint2*>(g_Hh + (size_t)sw3.x * D) + lane);
        fma_h4(acc, r0, __int_as_float(sw0.y));
        fma_h4(acc, r1, __int_as_float(sw1.y));
        fma_h4(acc, r2, __int_as_float(sw2.y));
        fma_h4(acc, r3, __int_as_float(sw3.y));
    }
    for (; e < end; ++e) {
        const int2 sw = __ldcs(&g_sw[e]);
        const uint2 r = __ldg(
            reinterpret_cast<const uint2*>(g_Hh + (size_t)sw.x * D) + lane);
        fma_h4(acc, r, __int_as_float(sw.y));
    }

    const float4 xv =
        __ldcs(reinterpret_cast<const float4*>(X + (size_t)gw * D) + lane);
    float4 o;
    o.x = fmaxf(acc.x, 0.f) + xv.x;
    o.y = fmaxf(acc.y, 0.f) + xv.y;
    o.z = fmaxf(acc.z, 0.f) + xv.z;
    o.w = fmaxf(acc.w, 0.f) + xv.w;
    __stcs(reinterpret_cast<float4*>(out + (size_t)gw * D) + lane, o);
}

// ===========================================================================
extern "C" void kernel_launch(void* const* d_in, const int* in_sizes, int n_in,
                              void* d_out, int out_size) {
    const float* X     = (const float*)d_in[0];
    const int*   esrc  = (const int*)d_in[1];
    const int*   edst  = (const int*)d_in[2];
    const float* ew    = (const float*)d_in[3];
    const float* gamma = (const float*)d_in[4];
    const float* beta  = (const float*)d_in[5];
    const float* W     = (const float*)d_in[6];
    const float* bias  = (const float*)d_in[7];
    float* out         = (float*)d_out;
    const int E        = in_sizes[1];

    cudaFuncSetAttribute(ln_linear_kernel,
                         cudaFuncAttributeMaxDynamicSharedMemorySize,
                         SMEM_BYTES);

    void* off_ptr = nullptr;
    cudaGetSymbolAddress(&off_ptr, g_off);
    cudaMemsetAsync(off_ptr, 0, (N_NODES + 1) * sizeof(int));

    const int n  = N_NODES + 1;
    const int nb = (n + 1023) / 1024;                 // 98

    hist_kernel<<<HIST_BLOCKS, 256>>>(edst, E);
    scan_chunk_kernel<<<nb, 1024>>>(n);
    scan_add_fused_kernel<<<nb, 1024>>>(n, nb);
    reorder_kernel<<<1024, 256>>>(esrc, edst, ew, E);

    ln_linear_kernel<<<(N_NODES + ROWS_PB - 1) / ROWS_PB, 256, SMEM_BYTES>>>(
        X, gamma, beta, W, bias);

    aggregate_kernel<<<(N_NODES * 32 + 255) / 256, 256>>>(X, out);
}

// round 13
// speedup vs baseline: 1.1759x; 1.0636x over previous
#include <cuda_runtime.h>
#include <cuda_fp16.h>
#include <stdint.h>

#define N_NODES 100000
#define N_EDGES 3200000
#define D 128
#define LN_EPS 1e-5f

// ---------------------------------------------------------------------------
// Device-global scratch (no allocations allowed).
// ---------------------------------------------------------------------------
__device__ __half g_Hh[(size_t)N_NODES * D];   // LN(X) @ W^T + b, fp16
__device__ int   g_off[N_NODES + 1];           // CSR offsets (by dst)
__device__ int   g_cur[N_NODES];               // bucket cursors
__device__ int2  g_sw[N_EDGES];                // packed (src, w_bits) sorted by dst
__device__ int   g_bsum[128];                  // scan block sums

// ---------------------------------------------------------------------------
// Host-side overlap context: one side stream + two fork/join events, created
// once at static init (host resources only; no device memory).
// ---------------------------------------------------------------------------
struct OverlapCtx {
    cudaStream_t s2;
    cudaEvent_t  e_fork, e_join;
    OverlapCtx() {
        cudaStreamCreateWithFlags(&s2, cudaStreamNonBlocking);
        cudaEventCreateWithFlags(&e_fork, cudaEventDisableTiming);
        cudaEventCreateWithFlags(&e_join, cudaEventDisableTiming);
    }
};
static OverlapCtx g_ctx;

// ===========================================================================
// Kernel A: standalone edge histogram (int4-vectorized).
// ===========================================================================
#define HIST_BLOCKS 512
__global__ void __launch_bounds__(256)
hist_kernel(const int* __restrict__ edst, int E) {
    const int n4     = E >> 2;
    const int4* p    = reinterpret_cast<const int4*>(edst);
    const int stride = HIST_BLOCKS * 256;
    const int gid    = blockIdx.x * 256 + threadIdx.x;
    for (int i = gid; i < n4; i += stride) {
        const int4 v = __ldcs(&p[i]);
        atomicAdd(&g_off[v.x + 1], 1);
        atomicAdd(&g_off[v.y + 1], 1);
        atomicAdd(&g_off[v.z + 1], 1);
        atomicAdd(&g_off[v.w + 1], 1);
    }
    for (int e = (n4 << 2) + gid; e < E; e += stride)      // tail (none for 3.2M)
        atomicAdd(&g_off[edst[e] + 1], 1);
}

// ===========================================================================
// Scan: chunk-scan + fused (bsum-prefix + add + cursor init)
// ===========================================================================
__device__ __forceinline__ int warp_incl_scan(int v, int lane) {
    #pragma unroll
    for (int off = 1; off < 32; off <<= 1) {
        int t = __shfl_up_sync(0xffffffffu, v, off);
        if (lane >= off) v += t;
    }
    return v;
}

__global__ void scan_chunk_kernel(int n) {        // blockDim = 1024
    __shared__ int wsum[32];
    const int tid  = threadIdx.x;
    const int lane = tid & 31;
    const int wid  = tid >> 5;
    const int gi   = blockIdx.x * 1024 + tid;
    int v = (gi < n) ? g_off[gi] : 0;
    v = warp_incl_scan(v, lane);
    if (lane == 31) wsum[wid] = v;
    __syncthreads();
    if (wid == 0) wsum[lane] = warp_incl_scan(wsum[lane], lane);
    __syncthreads();
    if (wid > 0) v += wsum[wid - 1];
    if (gi < n) g_off[gi] = v;
    if (tid == 1023) g_bsum[blockIdx.x] = v;
}

__global__ void scan_add_fused_kernel(int n, int nb) {   // blockDim = 1024
    __shared__ int bs[128];
    const int tid = threadIdx.x;
    if (tid < nb) bs[tid] = g_bsum[tid];
    __syncthreads();
    if (tid == 0) {
        int run = 0;
        for (int i = 0; i < nb; ++i) { run += bs[i]; bs[i] = run; }
    }
    __syncthreads();
    const int gi = blockIdx.x * 1024 + tid;
    if (gi >= n) return;
    const int add = (blockIdx.x > 0) ? bs[blockIdx.x - 1] : 0;
    const int val = g_off[gi] + add;
    g_off[gi] = val;
    if (gi < N_NODES) g_cur[gi] = val;
}

// ===========================================================================
// Kernel C: edge reorder into dst-CSR buckets.
// ===========================================================================
__global__ void __launch_bounds__(256)
reorder_kernel(const int* __restrict__ esrc,
               const int* __restrict__ edst,
               const float* __restrict__ ew, int E) {
    const int stride = gridDim.x * blockDim.x;
    for (int e = blockIdx.x * blockDim.x + threadIdx.x; e < E; e += stride) {
        const int dst = __ldcs(&edst[e]);
        const int pos = atomicAdd(&g_cur[dst], 1);
        g_sw[pos] = make_int2(__ldcs(&esrc[e]), __float_as_int(__ldcs(&ew[e])));
    }
}

// ===========================================================================
// Kernel D: fused LayerNorm + Linear (X -> g_Hh, fp16), f32x2 packed FMA.
//   ROWS_PB=64 rows/block, 256 threads, 1 block/SM (131KB smem).
// ===========================================================================
#define ROWS_PB 64
#define WS_PITCH 132
#define XN2_OFF (128 * WS_PITCH)                   // in floats
#define SMEM_BYTES ((128 * WS_PITCH) * 4 + ROWS_PB * D * 8)

__global__ void __launch_bounds__(256, 1)
ln_linear_kernel(const float* __restrict__ X,
                 const float* __restrict__ gamma,
                 const float* __restrict__ beta,
                 const float* __restrict__ W,
                 const float* __restrict__ bias) {
    extern __shared__ float smem[];
    float*  Ws  = smem;                                       // [128][132]
    float2* xn2 = reinterpret_cast<float2*>(smem + XN2_OFF);  // splatted {x,x}

    const int tid  = threadIdx.x;
    const int lane = tid & 31;
    const int warp = tid >> 5;
    const int row0 = blockIdx.x * ROWS_PB;

    // Load + transpose W into smem.
    for (int i = tid; i < 128 * 128; i += 256) {
        int o = i >> 7;
        int d = i & 127;
        Ws[d * WS_PITCH + o] = W[i];
    }

    // LayerNorm: 8 warps x 8 rows each; write splatted pairs {h,h}.
    #pragma unroll
    for (int rr = 0; rr < ROWS_PB / 8; ++rr) {
        const int r   = warp + rr * 8;
        const int row = row0 + r;
        float4 v = make_float4(0.f, 0.f, 0.f, 0.f);
        if (row < N_NODES)
            v = reinterpret_cast<const float4*>(X + (size_t)row * D)[lane];
        float s  = v.x + v.y + v.z + v.w;
        float sq = v.x * v.x + v.y * v.y + v.z * v.z + v.w * v.w;
        #pragma unroll
        for (int off = 16; off; off >>= 1) {
            s  += __shfl_xor_sync(0xffffffffu, s,  off);
            sq += __shfl_xor_sync(0xffffffffu, sq, off);
        }
        const float mu  = s * (1.0f / D);
        const float var = sq * (1.0f / D) - mu * mu;
        const float inv = rsqrtf(var + LN_EPS);
        const float4 g  = reinterpret_cast<const float4*>(gamma)[lane];
        const float4 be = reinterpret_cast<const float4*>(beta)[lane];
        float h0 = (v.x - mu) * inv * g.x + be.x;
        float h1 = (v.y - mu) * inv * g.y + be.y;
        float h2 = (v.z - mu) * inv * g.z + be.z;
        float h3 = (v.w - mu) * inv * g.w + be.w;
        float2* xp = xn2 + r * D + lane * 4;
        xp[0] = make_float2(h0, h0);
        xp[1] = make_float2(h1, h1);
        xp[2] = make_float2(h2, h2);
        xp[3] = make_float2(h3, h3);
    }
    __syncthreads();

    // GEMM: thread (tr, tc): rows tr*8..+7, cols tc*4..+3. f32x2 packed FMA.
    const int tc = tid & 31;
    const int tr = tid >> 5;

    unsigned long long acc01[8], acc23[8];
    #pragma unroll
    for (int i = 0; i < 8; ++i) { acc01[i] = 0ull; acc23[i] = 0ull; }

    const unsigned long long* xbase =
        reinterpret_cast<const unsigned long long*>(xn2) + tr * 8 * D;
    const float* wbase = Ws + (tc << 2);

    #pragma unroll 2
    for (int d = 0; d < D; ++d) {
        const ulonglong2 wv =
            *reinterpret_cast<const ulonglong2*>(wbase + d * WS_PITCH);
        #pragma unroll
        for (int r = 0; r < 8; ++r) {
            const unsigned long long xs = xbase[r * D + d];   // {x,x} broadcast
            asm("fma.rn.f32x2 %0, %1, %2, %0;" : "+l"(acc01[r]) : "l"(xs), "l"(wv.x));
            asm("fma.rn.f32x2 %0, %1, %2, %0;" : "+l"(acc23[r]) : "l"(xs), "l"(wv.y));
        }
    }

    const float4 bv = reinterpret_cast<const float4*>(bias)[tc];
    #pragma unroll
    for (int r = 0; r < 8; ++r) {
        const int row = row0 + tr * 8 + r;
        if (row < N_NODES) {
            const float hx = __uint_as_float((unsigned)(acc01[r] & 0xffffffffull)) + bv.x;
            const float hy = __uint_as_float((unsigned)(acc01[r] >> 32))           + bv.y;
            const float hz = __uint_as_float((unsigned)(acc23[r] & 0xffffffffull)) + bv.z;
            const float hw = __uint_as_float((unsigned)(acc23[r] >> 32))           + bv.w;
            const __half2 p01 = __floats2half2_rn(hx, hy);
            const __half2 p23 = __floats2half2_rn(hz, hw);
            uint2 st;
            st.x = *reinterpret_cast<const unsigned*>(&p01);
            st.y = *reinterpret_cast<const unsigned*>(&p23);
            reinterpret_cast<uint2*>(g_Hh + (size_t)row * D)[tc] = st;
        }
    }
}

// ===========================================================================
// Kernel E: aggregate. One warp per dst node, unroll-4 front-batched gathers.
//   out = relu(sum w*H[src]) + X.
// ===========================================================================
__device__ __forceinline__ void fma_h4(float4& acc, uint2 raw, float w) {
    const __half2 a = *reinterpret_cast<const __half2*>(&raw.x);
    const __half2 b = *reinterpret_cast<const __half2*>(&raw.y);
    const float2 f01 = __half22float2(a);
    const float2 f23 = __half22float2(b);
    acc.x = fmaf(w, f01.x, acc.x);
    acc.y = fmaf(w, f01.y, acc.y);
    acc.z = fmaf(w, f23.x, acc.z);
    acc.w = fmaf(w, f23.y, acc.w);
}

__global__ void __launch_bounds__(256)
aggregate_kernel(const float* __restrict__ X, float* __restrict__ out) {
    const int gw = (blockIdx.x * blockDim.x + threadIdx.x) >> 5;
    if (gw >= N_NODES) return;
    const int lane = threadIdx.x & 31;

    const int beg = g_off[gw];
    const int end = g_off[gw + 1];

    float4 acc = make_float4(0.f, 0.f, 0.f, 0.f);
    int e = beg;

    for (; e + 3 < end; e += 4) {
        const int2 sw0 = __ldcs(&g_sw[e]);
        const int2 sw1 = __ldcs(&g_sw[e + 1]);
        const int2 sw2 = __ldcs(&g_sw[e + 2]);
        const int2 sw3 = __ldcs(&g_sw[e + 3]);
        const uint2 r0 = __ldg(
            reinterpret_cast<const uint2*>(g_Hh + (size_t)sw0.x * D) + lane);
        const uint2 r1 = __ldg(
            reinterpret_cast<const uint2*>(g_Hh + (size_t)sw1.x * D) + lane);
        const uint2 r2 = __ldg(
            reinterpret_cast<const uint2*>(g_Hh + (size_t)sw2.x * D) + lane);
        const uint2 r3 = __ldg(
            reinterpret_cast<const uint2*>(g_Hh + (size_t)sw3.x * D) + lane);
        fma_h4(acc, r0, __int_as_float(sw0.y));
        fma_h4(acc, r1, __int_as_float(sw1.y));
        fma_h4(acc, r2, __int_as_float(sw2.y));
        fma_h4(acc, r3, __int_as_float(sw3.y));
    }
    for (; e < end; ++e) {
        const int2 sw = __ldcs(&g_sw[e]);
        const uint2 r = __ldg(
            reinterpret_cast<const uint2*>(g_Hh + (size_t)sw.x * D) + lane);
        fma_h4(acc, r, __int_as_float(sw.y));
    }

    const float4 xv =
        __ldcs(reinterpret_cast<const float4*>(X + (size_t)gw * D) + lane);
    float4 o;
    o.x = fmaxf(acc.x, 0.f) + xv.x;
    o.y = fmaxf(acc.y, 0.f) + xv.y;
    o.z = fmaxf(acc.z, 0.f) + xv.z;
    o.w = fmaxf(acc.w, 0.f) + xv.w;
    __stcs(reinterpret_cast<float4*>(out + (size_t)gw * D) + lane, o);
}

// ===========================================================================
extern "C" void kernel_launch(void* const* d_in, const int* in_sizes, int n_in,
                              void* d_out, int out_size) {
    const float* X     = (const float*)d_in[0];
    const int*   esrc  = (const int*)d_in[1];
    const int*   edst  = (const int*)d_in[2];
    const float* ew    = (const float*)d_in[3];
    const float* gamma = (const float*)d_in[4];
    const float* beta  = (const float*)d_in[5];
    const float* W     = (const float*)d_in[6];
    const float* bias  = (const float*)d_in[7];
    float* out         = (float*)d_out;
    const int E        = in_sizes[1];

    cudaFuncSetAttribute(ln_linear_kernel,
                         cudaFuncAttributeMaxDynamicSharedMemorySize,
                         SMEM_BYTES);

    void* off_ptr = nullptr;
    cudaGetSymbolAddress(&off_ptr, g_off);

    const int n  = N_NODES + 1;
    const int nb = (n + 1023) / 1024;                 // 98

    // --- fork: CSR chain on side stream, GEMM on main (legacy) stream ----
    cudaEventRecord(g_ctx.e_fork, 0);
    cudaStreamWaitEvent(g_ctx.s2, g_ctx.e_fork, 0);

    cudaMemsetAsync(off_ptr, 0, n * sizeof(int), g_ctx.s2);
    hist_kernel<<<HIST_BLOCKS, 256, 0, g_ctx.s2>>>(edst, E);
    scan_chunk_kernel<<<nb, 1024, 0, g_ctx.s2>>>(n);
    scan_add_fused_kernel<<<nb, 1024, 0, g_ctx.s2>>>(n, nb);
    reorder_kernel<<<1024, 256, 0, g_ctx.s2>>>(esrc, edst, ew, E);
    cudaEventRecord(g_ctx.e_join, g_ctx.s2);

    // Concurrent with the CSR chain: compute-bound GEMM.
    ln_linear_kernel<<<(N_NODES + ROWS_PB - 1) / ROWS_PB, 256, SMEM_BYTES>>>(
        X, gamma, beta, W, bias);

    // --- join: aggregate needs both H and the CSR --------------------------
    cudaStreamWaitEvent(0, g_ctx.e_join, 0);
    aggregate_kernel<<<(N_NODES * 32 + 255) / 256, 256>>>(X, out);
}

// round 14
// speedup vs baseline: 1.6893x; 1.4366x over previous
#include <cuda_runtime.h>
#include <cuda_fp16.h>
#include <mma.h>
#include <stdint.h>

using namespace nvcuda;

#define N_NODES 100000
#define N_EDGES 3200000
#define D 128
#define LN_EPS 1e-5f

// ---------------------------------------------------------------------------
// Device-global scratch (no allocations allowed).
// ---------------------------------------------------------------------------
__device__ __half g_Hh[(size_t)N_NODES * D];   // LN(X) @ W^T + b, fp16
__device__ int   g_off[N_NODES + 1];           // CSR offsets (by dst)
__device__ int   g_cur[N_NODES];               // bucket cursors
__device__ int2  g_sw[N_EDGES];                // packed (src, w_bits) sorted by dst
__device__ int   g_bsum[128];                  // scan block sums

// ---------------------------------------------------------------------------
// Host-side overlap context (host resources only; created once).
// ---------------------------------------------------------------------------
struct OverlapCtx {
    cudaStream_t s2;
    cudaEvent_t  e_fork, e_join;
    OverlapCtx() {
        cudaStreamCreateWithFlags(&s2, cudaStreamNonBlocking);
        cudaEventCreateWithFlags(&e_fork, cudaEventDisableTiming);
        cudaEventCreateWithFlags(&e_join, cudaEventDisableTiming);
    }
};
static OverlapCtx g_ctx;

// ===========================================================================
// Kernel A: standalone edge histogram (int4-vectorized).
// ===========================================================================
#define HIST_BLOCKS 512
__global__ void __launch_bounds__(256)
hist_kernel(const int* __restrict__ edst, int E) {
    const int n4     = E >> 2;
    const int4* p    = reinterpret_cast<const int4*>(edst);
    const int stride = HIST_BLOCKS * 256;
    const int gid    = blockIdx.x * 256 + threadIdx.x;
    for (int i = gid; i < n4; i += stride) {
        const int4 v = __ldcs(&p[i]);
        atomicAdd(&g_off[v.x + 1], 1);
        atomicAdd(&g_off[v.y + 1], 1);
        atomicAdd(&g_off[v.z + 1], 1);
        atomicAdd(&g_off[v.w + 1], 1);
    }
    for (int e = (n4 << 2) + gid; e < E; e += stride)
        atomicAdd(&g_off[edst[e] + 1], 1);
}

// ===========================================================================
// Scan: chunk-scan + fused (bsum-prefix + add + cursor init)
// ===========================================================================
__device__ __forceinline__ int warp_incl_scan(int v, int lane) {
    #pragma unroll
    for (int off = 1; off < 32; off <<= 1) {
        int t = __shfl_up_sync(0xffffffffu, v, off);
        if (lane >= off) v += t;
    }
    return v;
}

__global__ void scan_chunk_kernel(int n) {        // blockDim = 1024
    __shared__ int wsum[32];
    const int tid  = threadIdx.x;
    const int lane = tid & 31;
    const int wid  = tid >> 5;
    const int gi   = blockIdx.x * 1024 + tid;
    int v = (gi < n) ? g_off[gi] : 0;
    v = warp_incl_scan(v, lane);
    if (lane == 31) wsum[wid] = v;
    __syncthreads();
    if (wid == 0) wsum[lane] = warp_incl_scan(wsum[lane], lane);
    __syncthreads();
    if (wid > 0) v += wsum[wid - 1];
    if (gi < n) g_off[gi] = v;
    if (tid == 1023) g_bsum[blockIdx.x] = v;
}

__global__ void scan_add_fused_kernel(int n, int nb) {   // blockDim = 1024
    __shared__ int bs[128];
    const int tid = threadIdx.x;
    if (tid < nb) bs[tid] = g_bsum[tid];
    __syncthreads();
    if (tid == 0) {
        int run = 0;
        for (int i = 0; i < nb; ++i) { run += bs[i]; bs[i] = run; }
    }
    __syncthreads();
    const int gi = blockIdx.x * 1024 + tid;
    if (gi >= n) return;
    const int add = (blockIdx.x > 0) ? bs[blockIdx.x - 1] : 0;
    const int val = g_off[gi] + add;
    g_off[gi] = val;
    if (gi < N_NODES) g_cur[gi] = val;
}

// ===========================================================================
// Kernel C: edge reorder into dst-CSR buckets.
// ===========================================================================
__global__ void __launch_bounds__(256)
reorder_kernel(const int* __restrict__ esrc,
               const int* __restrict__ edst,
               const float* __restrict__ ew, int E) {
    const int stride = gridDim.x * blockDim.x;
    for (int e = blockIdx.x * blockDim.x + threadIdx.x; e < E; e += stride) {
        const int dst = __ldcs(&edst[e]);
        const int pos = atomicAdd(&g_cur[dst], 1);
        g_sw[pos] = make_int2(__ldcs(&esrc[e]), __float_as_int(__ldcs(&ew[e])));
    }
}

// ===========================================================================
// Kernel D: fused LayerNorm + Linear (X -> g_Hh), fp16 tensor-core GEMM.
//   64 rows/block, 256 threads (8 warps).
//   Warp w: C row-tile (w>>1)*16, col-group (w&1)*64, four 16x16 tiles, K=128.
//   B fragments load straight from row-major W (as col_major), no transpose.
// ===========================================================================
#define ROWS_PB 64
#define W_LD 136                                   // halfs, pad 8
#define XN_LD 136
#define WH_HALFS (128 * W_LD)                      // 17408 halfs = 34816 B
#define XN_HALFS (ROWS_PB * XN_LD)                 //  8704 halfs = 17408 B
#define STAGE_OFF_B ((WH_HALFS + XN_HALFS) * 2)    // 52224 B (16B aligned)
#define SMEM_BYTES (STAGE_OFF_B + 8 * 256 * 4)     // + 8KB stage = 60416 B

__global__ void __launch_bounds__(256, 2)
ln_linear_kernel(const float* __restrict__ X,
                 const float* __restrict__ gamma,
                 const float* __restrict__ beta,
                 const float* __restrict__ W,
                 const float* __restrict__ bias) {
    extern __shared__ char smem[];
    __half* Wh = reinterpret_cast<__half*>(smem);              // [128][136]
    __half* Xn = Wh + WH_HALFS;                                // [64][136]
    float* stage = reinterpret_cast<float*>(smem + STAGE_OFF_B);

    const int tid  = threadIdx.x;
    const int lane = tid & 31;
    const int warp = tid >> 5;
    const int row0 = blockIdx.x * ROWS_PB;

    // ---- W -> fp16 smem: Wh[o*W_LD + d] = W[o][d] (straight, padded) ----
    {
        const float4* W4 = reinterpret_cast<const float4*>(W);
        for (int i = tid; i < 128 * 32; i += 256) {
            const int o  = i >> 5;
            const int d4 = (i & 31) << 2;
            const float4 w = W4[i];
            const __half2 p0 = __floats2half2_rn(w.x, w.y);
            const __half2 p1 = __floats2half2_rn(w.z, w.w);
            uint2 st;
            st.x = *reinterpret_cast<const unsigned*>(&p0);
            st.y = *reinterpret_cast<const unsigned*>(&p1);
            *reinterpret_cast<uint2*>(Wh + o * W_LD + d4) = st;
        }
    }

    // ---- LayerNorm: 8 warps x 8 rows; write fp16 rows into Xn -----------
    #pragma unroll
    for (int rr = 0; rr < ROWS_PB / 8; ++rr) {
        const int r   = warp + rr * 8;
        const int row = row0 + r;
        float4 v = make_float4(0.f, 0.f, 0.f, 0.f);
        if (row < N_NODES)
            v = reinterpret_cast<const float4*>(X + (size_t)row * D)[lane];
        float s  = v.x + v.y + v.z + v.w;
        float sq = v.x * v.x + v.y * v.y + v.z * v.z + v.w * v.w;
        #pragma unroll
        for (int off = 16; off; off >>= 1) {
            s  += __shfl_xor_sync(0xffffffffu, s,  off);
            sq += __shfl_xor_sync(0xffffffffu, sq, off);
        }
        const float mu  = s * (1.0f / D);
        const float var = sq * (1.0f / D) - mu * mu;
        const float inv = rsqrtf(var + LN_EPS);
        const float4 g  = reinterpret_cast<const float4*>(gamma)[lane];
        const float4 be = reinterpret_cast<const float4*>(beta)[lane];
        const float h0 = (v.x - mu) * inv * g.x + be.x;
        const float h1 = (v.y - mu) * inv * g.y + be.y;
        const float h2 = (v.z - mu) * inv * g.z + be.z;
        const float h3 = (v.w - mu) * inv * g.w + be.w;
        const __half2 p0 = __floats2half2_rn(h0, h1);
        const __half2 p1 = __floats2half2_rn(h2, h3);
        uint2 st;
        st.x = *reinterpret_cast<const unsigned*>(&p0);
        st.y = *reinterpret_cast<const unsigned*>(&p1);
        *reinterpret_cast<uint2*>(Xn + r * XN_LD + (lane << 2)) = st;
    }
    __syncthreads();

    // ---- tensor-core GEMM: H = Xn @ W^T ---------------------------------
    const int r16 = warp >> 1;                 // row-tile 0..3
    const int cb  = (warp & 1) * 64;           // col base 0 or 64

    wmma::fragment<wmma::accumulator, 16, 16, 16, float> c[4];
    #pragma unroll
    for (int ct = 0; ct < 4; ++ct) wmma::fill_fragment(c[ct], 0.0f);

    #pragma unroll
    for (int k0 = 0; k0 < 8; ++k0) {
        wmma::fragment<wmma::matrix_a, 16, 16, 16, __half, wmma::row_major> a;
        wmma::load_matrix_sync(a, Xn + r16 * 16 * XN_LD + k0 * 16, XN_LD);
        #pragma unroll
        for (int ct = 0; ct < 4; ++ct) {
            wmma::fragment<wmma::matrix_b, 16, 16, 16, __half, wmma::col_major> b;
            wmma::load_matrix_sync(b, Wh + (cb + ct * 16) * W_LD + k0 * 16, W_LD);
            wmma::mma_sync(c[ct], a, b, c[ct]);
        }
    }

    // ---- epilogue: +bias, fp16, store ----------------------------------
    float* st = stage + warp * 256;
    const int rt = lane >> 1;                  // row in tile 0..15
    const int ch = (lane & 1) * 8;             // col half 0/8
    #pragma unroll
    for (int ct = 0; ct < 4; ++ct) {
        wmma::store_matrix_sync(st, c[ct], 16, wmma::mem_row_major);
        __syncwarp();
        const int grow = row0 + r16 * 16 + rt;
        if (grow < N_NODES) {
            const int gcol = cb + ct * 16 + ch;
            float v[8];
            #pragma unroll
            for (int j = 0; j < 8; ++j)
                v[j] = st[rt * 16 + ch + j] + __ldg(&bias[gcol + j]);
            const __half2 q0 = __floats2half2_rn(v[0], v[1]);
            const __half2 q1 = __floats2half2_rn(v[2], v[3]);
            const __half2 q2 = __floats2half2_rn(v[4], v[5]);
            const __half2 q3 = __floats2half2_rn(v[6], v[7]);
            uint4 pkt;
            pkt.x = *reinterpret_cast<const unsigned*>(&q0);
            pkt.y = *reinterpret_cast<const unsigned*>(&q1);
            pkt.z = *reinterpret_cast<const unsigned*>(&q2);
            pkt.w = *reinterpret_cast<const unsigned*>(&q3);
            *reinterpret_cast<uint4*>(g_Hh + (size_t)grow * D + gcol) = pkt;
        }
        __syncwarp();
    }
}

// ===========================================================================
// Kernel E: aggregate. One warp per dst node, unroll-4 front-batched gathers.
//   out = relu(sum w*H[src]) + X.
// ===========================================================================
__device__ __forceinline__ void fma_h4(float4& acc, uint2 raw, float w) {
    const __half2 a = *reinterpret_cast<const __half2*>(&raw.x);
    const __half2 b = *reinterpret_cast<const __half2*>(&raw.y);
    const float2 f01 = __half22float2(a);
    const float2 f23 = __half22float2(b);
    acc.x = fmaf(w, f01.x, acc.x);
    acc.y = fmaf(w, f01.y, acc.y);
    acc.z = fmaf(w, f23.x, acc.z);
    acc.w = fmaf(w, f23.y, acc.w);
}

__global__ void __launch_bounds__(256)
aggregate_kernel(const float* __restrict__ X, float* __restrict__ out) {
    const int gw = (blockIdx.x * blockDim.x + threadIdx.x) >> 5;
    if (gw >= N_NODES) return;
    const int lane = threadIdx.x & 31;

    const int beg = g_off[gw];
    const int end = g_off[gw + 1];

    float4 acc = make_float4(0.f, 0.f, 0.f, 0.f);
    int e = beg;

    for (; e + 3 < end; e += 4) {
        const int2 sw0 = __ldcs(&g_sw[e]);
        const int2 sw1 = __ldcs(&g_sw[e + 1]);
        const int2 sw2 = __ldcs(&g_sw[e + 2]);
        const int2 sw3 = __ldcs(&g_sw[e + 3]);
        const uint2 r0 = __ldg(
            reinterpret_cast<const uint2*>(g_Hh + (size_t)sw0.x * D) + lane);
        const uint2 r1 = __ldg(
            reinterpret_cast<const uint2*>(g_Hh + (size_t)sw1.x * D) + lane);
        const uint2 r2 = __ldg(
            reinterpret_cast<const uint2*>(g_Hh + (size_t)sw2.x * D) + lane);
        const uint2 r3 = __ldg(
            reinterpret_cast<const uint2*>(g_Hh + (size_t)sw3.x * D) + lane);
        fma_h4(acc, r0, __int_as_float(sw0.y));
        fma_h4(acc, r1, __int_as_float(sw1.y));
        fma_h4(acc, r2, __int_as_float(sw2.y));
        fma_h4(acc, r3, __int_as_float(sw3.y));
    }
    for (; e < end; ++e) {
        const int2 sw = __ldcs(&g_sw[e]);
        const uint2 r = __ldg(
            reinterpret_cast<const uint2*>(g_Hh + (size_t)sw.x * D) + lane);
        fma_h4(acc, r, __int_as_float(sw.y));
    }

    const float4 xv =
        __ldcs(reinterpret_cast<const float4*>(X + (size_t)gw * D) + lane);
    float4 o;
    o.x = fmaxf(acc.x, 0.f) + xv.x;
    o.y = fmaxf(acc.y, 0.f) + xv.y;
    o.z = fmaxf(acc.z, 0.f) + xv.z;
    o.w = fmaxf(acc.w, 0.f) + xv.w;
    __stcs(reinterpret_cast<float4*>(out + (size_t)gw * D) + lane, o);
}

// ===========================================================================
extern "C" void kernel_launch(void* const* d_in, const int* in_sizes, int n_in,
                              void* d_out, int out_size) {
    const float* X     = (const float*)d_in[0];
    const int*   esrc  = (const int*)d_in[1];
    const int*   edst  = (const int*)d_in[2];
    const float* ew    = (const float*)d_in[3];
    const float* gamma = (const float*)d_in[4];
    const float* beta  = (const float*)d_in[5];
    const float* W     = (const float*)d_in[6];
    const float* bias  = (const float*)d_in[7];
    float* out         = (float*)d_out;
    const int E        = in_sizes[1];

    cudaFuncSetAttribute(ln_linear_kernel,
                         cudaFuncAttributeMaxDynamicSharedMemorySize,
                         SMEM_BYTES);

    void* off_ptr = nullptr;
    cudaGetSymbolAddress(&off_ptr, g_off);

    const int n  = N_NODES + 1;
    const int nb = (n + 1023) / 1024;                 // 98

    // --- fork: CSR chain on side stream, GEMM on main stream ---------------
    cudaEventRecord(g_ctx.e_fork, 0);
    cudaStreamWaitEvent(g_ctx.s2, g_ctx.e_fork, 0);

    cudaMemsetAsync(off_ptr, 0, n * sizeof(int), g_ctx.s2);
    hist_kernel<<<HIST_BLOCKS, 256, 0, g_ctx.s2>>>(edst, E);
    scan_chunk_kernel<<<nb, 1024, 0, g_ctx.s2>>>(n);
    scan_add_fused_kernel<<<nb, 1024, 0, g_ctx.s2>>>(n, nb);
    reorder_kernel<<<1024, 256, 0, g_ctx.s2>>>(esrc, edst, ew, E);
    cudaEventRecord(g_ctx.e_join, g_ctx.s2);

    ln_linear_kernel<<<(N_NODES + ROWS_PB - 1) / ROWS_PB, 256, SMEM_BYTES>>>(
        X, gamma, beta, W, bias);

    // --- join ------------------------------------------------------------
    cudaStreamWaitEvent(0, g_ctx.e_join, 0);
    aggregate_kernel<<<(N_NODES * 32 + 255) / 256, 256>>>(X, out);
}